// round 1
// baseline (speedup 1.0000x reference)
#include <cuda_runtime.h>

#define NB 4096      // batch (bs * n_node)
#define TT 64        // num_past
#define DD 256       // hidden_nf
#define LD 260       // padded row stride (floats) for 64x256 smem tiles
#define SST 65       // padded row stride for 64x64 scores tile

typedef unsigned long long u64;

__device__ __forceinline__ void ffma2(u64 &d, u64 a, u64 b) {
    asm("fma.rn.f32x2 %0, %1, %2, %0;" : "+l"(d) : "l"(a), "l"(b));
}
__device__ __forceinline__ u64 pack2(float x, float y) {
    u64 r; asm("mov.b64 %0, {%1,%2};" : "=l"(r) : "f"(x), "f"(y)); return r;
}
__device__ __forceinline__ float2 unpack2(u64 v) {
    float2 f; asm("mov.b64 {%0,%1}, %2;" : "=f"(f.x), "=f"(f.y) : "l"(v)); return f;
}

// C(64x256) = relu(A(64x256 smem) @ W(256x256 gmem) + b). dst may alias src.
// 256 threads: thread (ty,tx) owns rows ty*8..+7, cols tx*8..+7.
__device__ void mlp_layer(float* dst, const float* src,
                          const float* __restrict__ W,
                          const float* __restrict__ bias) {
    const int tid = threadIdx.x;
    const int ty = tid >> 5;
    const int tx = tid & 31;
    const int col0 = tx * 8;

    u64 acc[8][4];
    {
        const ulonglong2* bp = (const ulonglong2*)(bias + col0);
        ulonglong2 b0 = bp[0], b1 = bp[1];
        u64 bi[4] = { b0.x, b0.y, b1.x, b1.y };
        #pragma unroll
        for (int r = 0; r < 8; r++)
            #pragma unroll
            for (int c = 0; c < 4; c++) acc[r][c] = bi[c];
    }

    const float* a_base = src + ty * 8 * LD;
    for (int kk = 0; kk < DD; kk += 4) {
        // hoist ALL loads of this iteration (A broadcast LDS.128, W LDG.128)
        float4 a[8];
        #pragma unroll
        for (int r = 0; r < 8; r++)
            a[r] = *(const float4*)(a_base + r * LD + kk);
        u64 wv[4][4];
        #pragma unroll
        for (int u = 0; u < 4; u++) {
            const ulonglong2* wp = (const ulonglong2*)(W + (kk + u) * DD + col0);
            ulonglong2 w0 = wp[0], w1 = wp[1];
            wv[u][0] = w0.x; wv[u][1] = w0.y; wv[u][2] = w1.x; wv[u][3] = w1.y;
        }
        #pragma unroll
        for (int u = 0; u < 4; u++) {
            #pragma unroll
            for (int r = 0; r < 8; r++) {
                float av = (u == 0) ? a[r].x : (u == 1) ? a[r].y : (u == 2) ? a[r].z : a[r].w;
                u64 ap = pack2(av, av);
                #pragma unroll
                for (int c = 0; c < 4; c++) ffma2(acc[r][c], ap, wv[u][c]);
            }
        }
    }
    __syncthreads();   // all reads done (allows dst == src)
    #pragma unroll
    for (int r = 0; r < 8; r++) {
        float o[8];
        #pragma unroll
        for (int c = 0; c < 4; c++) {
            float2 f = unpack2(acc[r][c]);
            o[2 * c]     = fmaxf(f.x, 0.f);
            o[2 * c + 1] = fmaxf(f.y, 0.f);
        }
        float* dp = dst + (ty * 8 + r) * LD + col0;
        *(float4*)dp       = make_float4(o[0], o[1], o[2], o[3]);
        *(float4*)(dp + 4) = make_float4(o[4], o[5], o[6], o[7]);
    }
    __syncthreads();
}

// scores = q @ k^T (64x64), then row softmax in place.
__device__ void attn_scores_softmax(float* s, const float* q, const float* k) {
    const int tid = threadIdx.x;
    const int ig = tid >> 4;   // 0..15
    const int jg = tid & 15;   // 0..15
    float acc[4][4];
    #pragma unroll
    for (int r = 0; r < 4; r++)
        #pragma unroll
        for (int c = 0; c < 4; c++) acc[r][c] = 0.f;

    const float* qb = q + ig * 4 * LD;
    const float* kb = k + jg * 4 * LD;
    for (int kk = 0; kk < DD; kk += 4) {
        float4 qa[4], ka[4];
        #pragma unroll
        for (int r = 0; r < 4; r++) qa[r] = *(const float4*)(qb + r * LD + kk);
        #pragma unroll
        for (int c = 0; c < 4; c++) ka[c] = *(const float4*)(kb + c * LD + kk);
        #pragma unroll
        for (int r = 0; r < 4; r++)
            #pragma unroll
            for (int c = 0; c < 4; c++) {
                float t = fmaf(qa[r].x, ka[c].x, acc[r][c]);
                t = fmaf(qa[r].y, ka[c].y, t);
                t = fmaf(qa[r].z, ka[c].z, t);
                acc[r][c] = fmaf(qa[r].w, ka[c].w, t);
            }
    }
    #pragma unroll
    for (int r = 0; r < 4; r++)
        #pragma unroll
        for (int c = 0; c < 4; c++)
            s[(ig * 4 + r) * SST + jg * 4 + c] = acc[r][c];
    __syncthreads();

    if (tid < TT) {
        float* row = s + tid * SST;
        float m = row[0];
        #pragma unroll 8
        for (int j = 1; j < TT; j++) m = fmaxf(m, row[j]);
        float sum = 0.f;
        #pragma unroll 8
        for (int j = 0; j < TT; j++) { float e = expf(row[j] - m); row[j] = e; sum += e; }
        float inv = 1.f / sum;
        #pragma unroll 8
        for (int j = 0; j < TT; j++) row[j] *= inv;
    }
    __syncthreads();
}

// cv[j] = dot(t[j,:], wc2)  (256 threads: 4 partial sums per row + shfl)
__device__ void cv_compute(float* cv, const float* t, const float* __restrict__ wc2) {
    const int tid = threadIdx.x;
    const int row = tid >> 2;
    const int part = tid & 3;
    const float* tr = t + row * LD + part * 64;
    const float* wr = wc2 + part * 64;
    float sum = 0.f;
    #pragma unroll
    for (int i = 0; i < 64; i += 4) {
        float4 a = *(const float4*)(tr + i);
        float4 w = *(const float4*)(wr + i);
        sum = fmaf(a.x, w.x, fmaf(a.y, w.y, fmaf(a.z, w.z, fmaf(a.w, w.w, sum))));
    }
    sum += __shfl_xor_sync(0xffffffffu, sum, 1);
    sum += __shfl_xor_sync(0xffffffffu, sum, 2);
    if (part == 0) cv[row] = sum;
    __syncthreads();
}

// out_h = h + alpha @ v   (64x256, written straight to gmem)
__device__ void h_out_write(float* __restrict__ outp, const float* s,
                            const float* v, const float* h) {
    const int tid = threadIdx.x;
    const int ty = tid >> 5;
    const int tx = tid & 31;
    const int col0 = tx * 8;
    u64 acc[8][4];
    #pragma unroll
    for (int r = 0; r < 8; r++)
        #pragma unroll
        for (int c = 0; c < 4; c++) acc[r][c] = 0ULL;

    for (int j = 0; j < TT; j++) {
        const ulonglong2* vp = (const ulonglong2*)(v + j * LD + col0);
        ulonglong2 v0 = vp[0], v1 = vp[1];
        u64 vv[4] = { v0.x, v0.y, v1.x, v1.y };
        #pragma unroll
        for (int r = 0; r < 8; r++) {
            float al = s[(ty * 8 + r) * SST + j];   // warp-broadcast
            u64 ap = pack2(al, al);
            #pragma unroll
            for (int c = 0; c < 4; c++) ffma2(acc[r][c], ap, vv[c]);
        }
    }
    #pragma unroll
    for (int r = 0; r < 8; r++) {
        const int row = ty * 8 + r;
        float4 h0 = *(const float4*)(h + row * LD + col0);
        float4 h1 = *(const float4*)(h + row * LD + col0 + 4);
        float2 f0 = unpack2(acc[r][0]), f1 = unpack2(acc[r][1]);
        float2 f2 = unpack2(acc[r][2]), f3 = unpack2(acc[r][3]);
        float* op = outp + row * DD + col0;
        *(float4*)op       = make_float4(h0.x + f0.x, h0.y + f0.y, h0.z + f1.x, h0.w + f1.y);
        *(float4*)(op + 4) = make_float4(h1.x + f2.x, h1.y + f2.y, h1.z + f3.x, h1.w + f3.y);
    }
}

// out_c[i] = coord[i] + sum_j alpha[i][j]*cv[j]*(coord[j]-coord[i])
__device__ void coord_out_write(float* __restrict__ outp, const float* s,
                                const float* cv, const float* c4) {
    const int tid = threadIdx.x;
    if (tid < TT) {
        float wsum = 0.f, a0 = 0.f, a1 = 0.f, a2 = 0.f;
        const float* row = s + tid * SST;
        #pragma unroll 8
        for (int j = 0; j < TT; j++) {
            float wv = row[j] * cv[j];
            wsum += wv;
            a0 = fmaf(wv, c4[j * 4 + 0], a0);
            a1 = fmaf(wv, c4[j * 4 + 1], a1);
            a2 = fmaf(wv, c4[j * 4 + 2], a2);
        }
        float cx = c4[tid * 4 + 0], cy = c4[tid * 4 + 1], cz = c4[tid * 4 + 2];
        float* o = outp + tid * 3;
        o[0] = cx + a0 - cx * wsum;
        o[1] = cy + a1 - cy * wsum;
        o[2] = cz + a2 - cz * wsum;
    }
}

extern __shared__ float smem[];

__global__ void __launch_bounds__(256, 1)
egcl_kernel(const float* __restrict__ h, const float* __restrict__ coord,
            const float* __restrict__ Wq1, const float* __restrict__ bq1,
            const float* __restrict__ Wq2, const float* __restrict__ bq2,
            const float* __restrict__ Wk1, const float* __restrict__ bk1,
            const float* __restrict__ Wk2, const float* __restrict__ bk2,
            const float* __restrict__ Wv1, const float* __restrict__ bv1,
            const float* __restrict__ Wv2, const float* __restrict__ bv2,
            const float* __restrict__ Wc1, const float* __restrict__ bc1,
            const float* __restrict__ wc2,
            float* __restrict__ out_h, float* __restrict__ out_c) {
    float* h_s  = smem;                    // 64*LD
    float* bufA = h_s  + TT * LD;          // 64*LD
    float* bufB = bufA + TT * LD;          // 64*LD
    float* s_s  = bufB + TT * LD;          // 64*SST
    float* c4   = s_s  + TT * SST;         // 64*4
    float* cv   = c4   + TT * 4;           // 64

    const int b = blockIdx.x;
    const int tid = threadIdx.x;

    // load h tile (coalesced float4) into padded smem
    const float4* hg = (const float4*)(h + (size_t)b * TT * DD);
    for (int i = tid; i < TT * DD / 4; i += 256) {
        int row = i >> 6;
        int c = (i & 63) << 2;
        *(float4*)(h_s + row * LD + c) = hg[i];
    }
    // load coord (64x3) into padded-by-4 smem
    const float* cg = coord + (size_t)b * TT * 3;
    if (tid < TT * 3) {
        int j = tid / 3, c = tid % 3;
        c4[j * 4 + c] = cg[tid];
    }
    __syncthreads();

    mlp_layer(bufA, h_s,  Wq1, bq1);   // q hidden
    mlp_layer(bufB, bufA, Wq2, bq2);   // q -> bufB
    mlp_layer(bufA, h_s,  Wk1, bk1);   // k hidden
    mlp_layer(bufA, bufA, Wk2, bk2);   // k -> bufA (in place)
    attn_scores_softmax(s_s, bufB, bufA);
    mlp_layer(bufB, h_s,  Wv1, bv1);   // v hidden (q dead)
    mlp_layer(bufB, bufB, Wv2, bv2);   // v -> bufB (in place)
    mlp_layer(bufA, bufB, Wc1, bc1);   // coord-mlp hidden (k dead)
    cv_compute(cv, bufA, wc2);
    h_out_write(out_h + (size_t)b * TT * DD, s_s, bufB, h_s);
    coord_out_write(out_c + (size_t)b * TT * 3, s_s, cv, c4);
}

extern "C" void kernel_launch(void* const* d_in, const int* in_sizes, int n_in,
                              void* d_out, int out_size) {
    const float* h     = (const float*)d_in[0];
    const float* coord = (const float*)d_in[1];
    const float* Wq1 = (const float*)d_in[2];
    const float* bq1 = (const float*)d_in[3];
    const float* Wq2 = (const float*)d_in[4];
    const float* bq2 = (const float*)d_in[5];
    const float* Wk1 = (const float*)d_in[6];
    const float* bk1 = (const float*)d_in[7];
    const float* Wk2 = (const float*)d_in[8];
    const float* bk2 = (const float*)d_in[9];
    const float* Wv1 = (const float*)d_in[10];
    const float* bv1 = (const float*)d_in[11];
    const float* Wv2 = (const float*)d_in[12];
    const float* bv2 = (const float*)d_in[13];
    const float* Wc1 = (const float*)d_in[14];
    const float* bc1 = (const float*)d_in[15];
    const float* wc2 = (const float*)d_in[16];

    float* out_h = (float*)d_out;                         // (B,T,D)
    float* out_c = out_h + (size_t)NB * TT * DD;          // (B,T,3) concatenated

    const size_t smem_bytes =
        (size_t)(3 * TT * LD + TT * SST + TT * 4 + TT) * sizeof(float);  // 217,600 B
    cudaFuncSetAttribute(egcl_kernel,
                         cudaFuncAttributeMaxDynamicSharedMemorySize,
                         (int)smem_bytes);

    egcl_kernel<<<NB, 256, smem_bytes>>>(
        h, coord, Wq1, bq1, Wq2, bq2, Wk1, bk1, Wk2, bk2,
        Wv1, bv1, Wv2, bv2, Wc1, bc1, wc2, out_h, out_c);
}